// round 6
// baseline (speedup 1.0000x reference)
#include <cuda_runtime.h>
#include <math.h>
#include <stdint.h>

#define BSZ    2048
#define LATENT 128
#define CCLS   8
#define HID    1024
#define DD     512
#define NMAXX  4096
#define NTG    128
#define NT     256

__constant__ int c_counts[CCLS] = {1024, 1536, 2048, 2560, 3072, 3584, 3840, 4096};

__device__ __align__(16) float g_h[BSZ * HID];
__device__ __align__(16) float g_t[BSZ * HID];
__device__ __align__(16) float g_logits[(size_t)BSZ * NMAXX];
__device__ __align__(16) float g_colmean[CCLS * DD];
__device__ int g_order[BSZ];
__device__ int g_class_off[CCLS + 1];

__device__ __forceinline__ float gelu_exact(float x) {
    return 0.5f * x * (1.0f + erff(x * 0.70710678118654752f));
}
__device__ __forceinline__ uint32_t f2b(float f) { return __float_as_uint(f); }

// exp(x) for |x| <~ 1 via degree-7 Taylor (FMA pipe, no MUFU).
__device__ __forceinline__ float exp_poly(float x) {
    float p = fmaf(x, 1.984126984e-4f, 1.388888889e-3f);   // 1/5040, 1/720
    p = fmaf(x, p, 8.333333333e-3f);                        // 1/120
    p = fmaf(x, p, 4.166666667e-2f);                        // 1/24
    p = fmaf(x, p, 1.666666667e-1f);                        // 1/6
    p = fmaf(x, p, 0.5f);
    p = fmaf(x, p, 1.0f);
    p = fmaf(x, p, 1.0f);
    return p;
}

__device__ __forceinline__ void mma8(float* d, const uint32_t* a, const uint32_t* b) {
    asm volatile(
        "mma.sync.aligned.m16n8k8.row.col.f32.tf32.tf32.f32 "
        "{%0,%1,%2,%3},{%4,%5,%6,%7},{%8,%9},{%0,%1,%2,%3};\n"
        : "+f"(d[0]), "+f"(d[1]), "+f"(d[2]), "+f"(d[3])
        : "r"(a[0]), "r"(a[1]), "r"(a[2]), "r"(a[3]), "r"(b[0]), "r"(b[1]));
}

__device__ __forceinline__ void cpa16(uint32_t dst, const float* src, bool pred) {
    int sz = pred ? 16 : 0;
    asm volatile("cp.async.cg.shared.global [%0], [%1], 16, %2;\n"
                 :: "r"(dst), "l"(src), "r"(sz));
}
#define CP_COMMIT asm volatile("cp.async.commit_group;\n")
#define CP_WAIT2  asm volatile("cp.async.wait_group 2;\n")

#define STAGES 4
#define ASTR 20
#define BSTR 136
#define BS_ELE (16 * BSTR)

// ================= T config: 64x64 tile, 128 thr (4 warps 2x2, warp 32x32) ==
#define BSTR_T 72
#define AS_ELE_T (64 * ASTR)
#define BS_ELE_T (16 * BSTR_T)

#define GEMM_PROLOG_T \
    __shared__ float As[STAGES][AS_ELE_T]; \
    __shared__ float Bs[STAGES][BS_ELE_T]; \
    int tid = threadIdx.x; int lane = tid & 31; int wid = tid >> 5; \
    int wm = (wid & 1) * 32, wn = (wid >> 1) * 32; \
    int g = lane >> 2, tg = lane & 3; \
    float acc[2][4][4] = {}; \
    uint32_t aBase = (uint32_t)__cvta_generic_to_shared(&As[0][0]); \
    uint32_t bBase = (uint32_t)__cvta_generic_to_shared(&Bs[0][0]); \
    int am = tid >> 1, ak = (tid & 1) * 8; \
    int bkr = tid >> 4, bnr = (tid & 15) * 4;

#define PREF_T(it, buf) do { int _k0 = (it) * 16; \
    cpa16(aBase + (uint32_t)((buf)*AS_ELE_T + am*ASTR + ak)*4,          rA0 + _k0 + ak, pa0); \
    cpa16(aBase + (uint32_t)((buf)*AS_ELE_T + am*ASTR + ak + 4)*4,      rA0 + _k0 + ak + 4, pa0); \
    cpa16(bBase + (uint32_t)((buf)*BS_ELE_T + bkr*BSTR_T + bnr)*4,      Bsrc + (size_t)(_k0+bkr)*ldb + bnr, true); \
    cpa16(bBase + (uint32_t)((buf)*BS_ELE_T + (bkr+8)*BSTR_T + bnr)*4,  Bsrc + (size_t)(_k0+bkr+8)*ldb + bnr, true); \
} while (0)

#define COMPUTE_T(cur) do { \
    const float* AsP = As[cur]; const float* BsP = Bs[cur]; \
    _Pragma("unroll") for (int kk = 0; kk < 2; ++kk) { \
        uint32_t afr[2][4]; \
        _Pragma("unroll") for (int mi = 0; mi < 2; ++mi) { \
            const float* ap = AsP + (wm + mi*16 + g)*ASTR + kk*8 + tg; \
            afr[mi][0] = f2b(ap[0]);  afr[mi][1] = f2b(ap[8*ASTR]); \
            afr[mi][2] = f2b(ap[4]);  afr[mi][3] = f2b(ap[8*ASTR + 4]); } \
        uint32_t bfr[4][2]; \
        _Pragma("unroll") for (int ni = 0; ni < 4; ++ni) { \
            const float* bp = BsP + (kk*8 + tg)*BSTR_T + wn + ni*8 + g; \
            bfr[ni][0] = f2b(bp[0]);  bfr[ni][1] = f2b(bp[4*BSTR_T]); } \
        _Pragma("unroll") for (int mi = 0; mi < 2; ++mi) \
        _Pragma("unroll") for (int ni = 0; ni < 4; ++ni) \
            mma8(acc[mi][ni], afr[mi], bfr[ni]); \
    } } while (0)

#define MAINLOOP_T(KITERS) \
    PREF_T(0, 0); CP_COMMIT; \
    PREF_T(1, 1); CP_COMMIT; \
    PREF_T(2, 2); CP_COMMIT; \
    for (int it = 0; it < (KITERS); ++it) { \
        int cur = it & 3; \
        CP_WAIT2; \
        __syncthreads(); \
        int nx = it + STAGES - 1; \
        if (nx < (KITERS)) { PREF_T(nx, nx & 3); } \
        CP_COMMIT; \
        COMPUTE_T(cur); \
    }

// ========================= small config: 64x128, 128 thr ====================
#define AS_ELE_S (64 * ASTR)
#define GEMM_PROLOG_S \
    __shared__ float As[STAGES][AS_ELE_S]; \
    __shared__ float Bs[STAGES][BS_ELE]; \
    int tid = threadIdx.x; int lane = tid & 31; int wid = tid >> 5; \
    int wm = (wid & 1) * 32, wn = (wid >> 1) * 64; \
    int g = lane >> 2, tg = lane & 3; \
    float acc[2][8][4] = {}; \
    uint32_t aBase = (uint32_t)__cvta_generic_to_shared(&As[0][0]); \
    uint32_t bBase = (uint32_t)__cvta_generic_to_shared(&Bs[0][0]); \
    int am = tid >> 1, ak = (tid & 1) * 8; \
    int bkr = tid >> 5, bnr = (tid & 31) * 4;

#define PREF_S(it, buf) do { int _k0 = (it) * 16; \
    cpa16(aBase + (uint32_t)((buf)*AS_ELE_S + am*ASTR + ak)*4,        rA0 + _k0 + ak, pa0); \
    cpa16(aBase + (uint32_t)((buf)*AS_ELE_S + am*ASTR + ak + 4)*4,    rA0 + _k0 + ak + 4, pa0); \
    cpa16(bBase + (uint32_t)((buf)*BS_ELE + bkr*BSTR + bnr)*4,        Bsrc + (size_t)(_k0+bkr)*ldb + bnr, true); \
    cpa16(bBase + (uint32_t)((buf)*BS_ELE + (bkr+4)*BSTR + bnr)*4,    Bsrc + (size_t)(_k0+bkr+4)*ldb + bnr, true); \
    cpa16(bBase + (uint32_t)((buf)*BS_ELE + (bkr+8)*BSTR + bnr)*4,    Bsrc + (size_t)(_k0+bkr+8)*ldb + bnr, true); \
    cpa16(bBase + (uint32_t)((buf)*BS_ELE + (bkr+12)*BSTR + bnr)*4,   Bsrc + (size_t)(_k0+bkr+12)*ldb + bnr, true); \
} while (0)

#define COMPUTE_S(cur) do { \
    const float* AsP = As[cur]; const float* BsP = Bs[cur]; \
    _Pragma("unroll") for (int kk = 0; kk < 2; ++kk) { \
        uint32_t afr[2][4]; \
        _Pragma("unroll") for (int mi = 0; mi < 2; ++mi) { \
            const float* ap = AsP + (wm + mi*16 + g)*ASTR + kk*8 + tg; \
            afr[mi][0] = f2b(ap[0]);  afr[mi][1] = f2b(ap[8*ASTR]); \
            afr[mi][2] = f2b(ap[4]);  afr[mi][3] = f2b(ap[8*ASTR + 4]); } \
        uint32_t bfr[8][2]; \
        _Pragma("unroll") for (int ni = 0; ni < 8; ++ni) { \
            const float* bp = BsP + (kk*8 + tg)*BSTR + wn + ni*8 + g; \
            bfr[ni][0] = f2b(bp[0]);  bfr[ni][1] = f2b(bp[4*BSTR]); } \
        _Pragma("unroll") for (int mi = 0; mi < 2; ++mi) \
        _Pragma("unroll") for (int ni = 0; ni < 8; ++ni) \
            mma8(acc[mi][ni], afr[mi], bfr[ni]); \
    } } while (0)

#define MAINLOOP_S(KITERS) \
    PREF_S(0, 0); CP_COMMIT; \
    PREF_S(1, 1); CP_COMMIT; \
    PREF_S(2, 2); CP_COMMIT; \
    for (int it = 0; it < (KITERS); ++it) { \
        int cur = it & 3; \
        CP_WAIT2; \
        __syncthreads(); \
        int nx = it + STAGES - 1; \
        if (nx < (KITERS)) { PREF_S(nx, nx & 3); } \
        CP_COMMIT; \
        COMPUTE_S(cur); \
    }

// ========================= large config: 128x128, 256 thr ===================
#define AS_ELE_L (128 * ASTR)
#define GEMM_PROLOG_L \
    __shared__ float As[STAGES][AS_ELE_L]; \
    __shared__ float Bs[STAGES][BS_ELE]; \
    int tid = threadIdx.x; int lane = tid & 31; int wid = tid >> 5; \
    int wm = (wid & 3) * 32, wn = (wid >> 2) * 64; \
    int g = lane >> 2, tg = lane & 3; \
    float acc[2][8][4] = {}; \
    uint32_t aBase = (uint32_t)__cvta_generic_to_shared(&As[0][0]); \
    uint32_t bBase = (uint32_t)__cvta_generic_to_shared(&Bs[0][0]); \
    int am = tid >> 1, ak = (tid & 1) * 8; \
    int bkr = tid >> 5, bnr = (tid & 31) * 4;

#define PREF_L(it, buf) do { int _k0 = (it) * 16; \
    cpa16(aBase + (uint32_t)((buf)*AS_ELE_L + am*ASTR + ak)*4,        rA0 + _k0 + ak, pa0); \
    cpa16(aBase + (uint32_t)((buf)*AS_ELE_L + am*ASTR + ak + 4)*4,    rA0 + _k0 + ak + 4, pa0); \
    cpa16(bBase + (uint32_t)((buf)*BS_ELE + bkr*BSTR + bnr)*4,        Bsrc + (size_t)(_k0+bkr)*ldb + bnr, true); \
    cpa16(bBase + (uint32_t)((buf)*BS_ELE + (bkr+8)*BSTR + bnr)*4,    Bsrc + (size_t)(_k0+bkr+8)*ldb + bnr, true); \
} while (0)

#define MAINLOOP_L(KITERS) \
    PREF_L(0, 0); CP_COMMIT; \
    PREF_L(1, 1); CP_COMMIT; \
    PREF_L(2, 2); CP_COMMIT; \
    for (int it = 0; it < (KITERS); ++it) { \
        int cur = it & 3; \
        CP_WAIT2; \
        __syncthreads(); \
        int nx = it + STAGES - 1; \
        if (nx < (KITERS)) { PREF_L(nx, nx & 3); } \
        CP_COMMIT; \
        COMPUTE_S(cur); \
    }

// ---------------------------------------------------------------------------
__global__ void group_kernel(const int* __restrict__ cls) {
    __shared__ int cnt[CCLS];
    __shared__ int off[CCLS + 1];
    int tid = threadIdx.x;
    if (tid < CCLS) cnt[tid] = 0;
    __syncthreads();
    for (int b = tid; b < BSZ; b += blockDim.x) atomicAdd(&cnt[cls[b]], 1);
    __syncthreads();
    if (tid == 0) {
        int s = 0;
        for (int c = 0; c < CCLS; c++) { off[c] = s; s += cnt[c]; }
        off[CCLS] = s;
        for (int c = 0; c <= CCLS; c++) g_class_off[c] = off[c];
    }
    __syncthreads();
    if (tid < CCLS) cnt[tid] = off[tid];
    __syncthreads();
    for (int b = tid; b < BSZ; b += blockDim.x) {
        int c = cls[b];
        int slot = atomicAdd(&cnt[c], 1);
        g_order[slot] = b;
    }
}

// ---------------------------------------------------------------------------
__global__ __launch_bounds__(NT) void k_colmean(const float* __restrict__ Xbuf) {
    int c = blockIdx.y;
    int dl = threadIdx.x & 63;
    int d = blockIdx.x * 64 + dl;
    int stripe = threadIdx.x >> 6;
    int cnt = c_counts[c];
    const float* X = Xbuf + (size_t)c * NMAXX * DD + d;
    float s = 0.f;
#pragma unroll 4
    for (int n = stripe; n < cnt; n += 4) s += X[(size_t)n * DD];
    __shared__ float red[NT];
    red[threadIdx.x] = s;
    __syncthreads();
    if (stripe == 0) {
        float tot = red[dl] + red[dl + 64] + red[dl + 128] + red[dl + 192];
        g_colmean[c * DD + d] = tot / (float)cnt;
    }
}

// ---------------------------------------------------------------------------
// Kernel 1: h = gelu(z @ W1[:128] + W1[128+cid] + b1)  (64x64 tiles)
// ---------------------------------------------------------------------------
__global__ __launch_bounds__(NTG, 4) void k_gemm_h(
    const float* __restrict__ z, const int* __restrict__ cls,
    const float* __restrict__ W1, const float* __restrict__ b1) {
    int m0 = blockIdx.y * 64, n0 = blockIdx.x * 64;
    GEMM_PROLOG_T
    const float* rA0 = z + (size_t)(m0 + am) * LATENT;
    bool pa0 = true;
    const float* Bsrc = W1 + n0; int ldb = HID;
    MAINLOOP_T(8)
#pragma unroll
    for (int mi = 0; mi < 2; ++mi)
#pragma unroll
    for (int r2 = 0; r2 < 2; ++r2) {
        int m = m0 + wm + mi * 16 + g + r2 * 8;
        int cid = cls[m];
        const float* wrow = W1 + (size_t)(LATENT + cid) * HID;
#pragma unroll
        for (int ni = 0; ni < 4; ++ni) {
            int n = n0 + wn + ni * 8 + tg * 2;
            float2 o;
            o.x = gelu_exact(acc[mi][ni][r2 * 2 + 0] + wrow[n] + b1[n]);
            o.y = gelu_exact(acc[mi][ni][r2 * 2 + 1] + wrow[n + 1] + b1[n + 1]);
            *(float2*)(g_h + (size_t)m * HID + n) = o;
        }
    }
}

// ---------------------------------------------------------------------------
// Kernel 2: t = gelu(h @ W2 + b2)  (64x64 tiles)
// ---------------------------------------------------------------------------
__global__ __launch_bounds__(NTG, 4) void k_gemm_t(
    const float* __restrict__ W2, const float* __restrict__ b2) {
    int m0 = blockIdx.y * 64, n0 = blockIdx.x * 64;
    GEMM_PROLOG_T
    const float* rA0 = g_h + (size_t)(m0 + am) * HID;
    bool pa0 = true;
    const float* Bsrc = W2 + n0; int ldb = HID;
    MAINLOOP_T(64)
#pragma unroll
    for (int mi = 0; mi < 2; ++mi)
#pragma unroll
    for (int r2 = 0; r2 < 2; ++r2) {
        int m = m0 + wm + mi * 16 + g + r2 * 8;
#pragma unroll
        for (int ni = 0; ni < 4; ++ni) {
            int n = n0 + wn + ni * 8 + tg * 2;
            float2 o;
            o.x = gelu_exact(acc[mi][ni][r2 * 2 + 0] + b2[n]);
            o.y = gelu_exact(acc[mi][ni][r2 * 2 + 1] + b2[n + 1]);
            *(float2*)(g_t + (size_t)m * HID + n) = o;
        }
    }
}

// ---------------------------------------------------------------------------
// Kernel 3: grouped logits, 128x128 tiles @ 256 threads
// ---------------------------------------------------------------------------
__global__ __launch_bounds__(NT, 2) void k_logits(
    const float* __restrict__ Wa, const float* __restrict__ ba) {
    int c = blockIdx.z;
    int off = g_class_off[c];
    int Bc = g_class_off[c + 1] - off;
    int mt = blockIdx.y, nt = blockIdx.x;
    if (mt * 128 >= Bc) return;
    int cnt = c_counts[c];
    if (nt * 128 >= cnt) return;
    int m0 = mt * 128, n0 = nt * 128;
    GEMM_PROLOG_L
    bool pa0 = (m0 + am) < Bc;
    const float* rA0 = pa0 ? g_t + (size_t)g_order[off + m0 + am] * HID : g_t;
    const float* Bsrc = Wa + (size_t)c * HID * NMAXX + n0; int ldb = NMAXX;
    MAINLOOP_L(64)
    const float* baC = ba + (size_t)c * NMAXX;
#pragma unroll
    for (int mi = 0; mi < 2; ++mi)
#pragma unroll
    for (int r2 = 0; r2 < 2; ++r2) {
        int ml = m0 + wm + mi * 16 + g + r2 * 8;
        if (ml < Bc) {
            size_t row = (size_t)(off + ml) * NMAXX;
#pragma unroll
            for (int ni = 0; ni < 8; ++ni) {
                int n = n0 + wn + ni * 8 + tg * 2;
                float2 bb = *(const float2*)(baC + n);
                float2 o;
                o.x = acc[mi][ni][r2 * 2 + 0] + bb.x;
                o.y = acc[mi][ni][r2 * 2 + 1] + bb.y;
                *(float2*)(g_logits + row + n) = o;
            }
        }
    }
}

// ---------------------------------------------------------------------------
// Kernel 4: softmax via poly-exp (no MUFU, no max pass — logits are tiny).
// Writes beta = alpha - 1/cnt in place. 1 global read + 1 write per row.
// ---------------------------------------------------------------------------
__global__ __launch_bounds__(NT) void k_softmax() {
    __shared__ float buf[NMAXX];
    __shared__ float reds[NT];
    int r = blockIdx.x;
    int c = 0;
#pragma unroll
    for (int i = 1; i < CCLS; i++)
        if (r >= g_class_off[i]) c = i;
    int cnt = c_counts[c];
    float* row = g_logits + (size_t)r * NMAXX;
    int tid = threadIdx.x;

    float s = 0.f;
    for (int i = tid * 4; i < cnt; i += NT * 4) {
        float4 v = *(const float4*)(row + i);
        v.x = exp_poly(v.x); v.y = exp_poly(v.y);
        v.z = exp_poly(v.z); v.w = exp_poly(v.w);
        s += v.x + v.y + v.z + v.w;
        *(float4*)(buf + i) = v;
    }
    reds[tid] = s;
    __syncthreads();
    for (int st = NT / 2; st > 0; st >>= 1) {
        if (tid < st) reds[tid] += reds[tid + st];
        __syncthreads();
    }
    float inv = 1.0f / reds[0];
    float invc = 1.0f / (float)cnt;

    for (int i = tid * 4; i < cnt; i += NT * 4) {
        float4 v = *(const float4*)(buf + i);
        v.x = fmaf(v.x, inv, -invc);
        v.y = fmaf(v.y, inv, -invc);
        v.z = fmaf(v.z, inv, -invc);
        v.w = fmaf(v.w, inv, -invc);
        *(float4*)(row + i) = v;
    }
}

// ---------------------------------------------------------------------------
// Kernel 5: out[order[r]] = colmean[c] + beta @ Xbuf[c]  (64x128 tiles)
// ---------------------------------------------------------------------------
__global__ __launch_bounds__(NTG, 4) void k_out(
    const float* __restrict__ Xbuf, float* __restrict__ out) {
    int c = blockIdx.z;
    int off = g_class_off[c];
    int Bc = g_class_off[c + 1] - off;
    int mt = blockIdx.y, nt = blockIdx.x;
    if (mt * 64 >= Bc) return;
    int cnt = c_counts[c];
    int m0 = mt * 64, n0 = nt * 128;
    GEMM_PROLOG_S
    bool pa0 = (m0 + am) < Bc;
    const float* rA0 = pa0 ? g_logits + (size_t)(off + m0 + am) * NMAXX : g_logits;
    const float* Bsrc = Xbuf + (size_t)c * NMAXX * DD + n0; int ldb = DD;
    int kit = cnt / 16;
    MAINLOOP_S(kit)
    const float* cm = g_colmean + c * DD;
#pragma unroll
    for (int mi = 0; mi < 2; ++mi)
#pragma unroll
    for (int r2 = 0; r2 < 2; ++r2) {
        int ml = m0 + wm + mi * 16 + g + r2 * 8;
        if (ml < Bc) {
            int b = g_order[off + ml];
#pragma unroll
            for (int ni = 0; ni < 8; ++ni) {
                int n = n0 + wn + ni * 8 + tg * 2;
                float2 m2 = *(const float2*)(cm + n);
                float2 o;
                o.x = acc[mi][ni][r2 * 2 + 0] + m2.x;
                o.y = acc[mi][ni][r2 * 2 + 1] + m2.y;
                *(float2*)(out + (size_t)b * DD + n) = o;
            }
        }
    }
}

// ---------------------------------------------------------------------------
extern "C" void kernel_launch(void* const* d_in, const int* in_sizes, int n_in,
                              void* d_out, int out_size) {
    const float* z   = (const float*)d_in[0];
    const int*   cls = (const int*)d_in[1];
    const float* W1  = (const float*)d_in[2];
    const float* b1  = (const float*)d_in[3];
    const float* W2  = (const float*)d_in[4];
    const float* b2  = (const float*)d_in[5];
    const float* Wa  = (const float*)d_in[6];
    const float* ba  = (const float*)d_in[7];
    const float* Xb  = (const float*)d_in[8];
    float* out = (float*)d_out;

    group_kernel<<<1, NT>>>(cls);
    k_colmean<<<dim3(DD / 64, CCLS), NT>>>(Xb);
    k_gemm_h<<<dim3(HID / 64, BSZ / 64), NTG>>>(z, cls, W1, b1);
    k_gemm_t<<<dim3(HID / 64, BSZ / 64), NTG>>>(W2, b2);
    k_logits<<<dim3(NMAXX / 128, BSZ / 128, CCLS), NT>>>(Wa, ba);
    k_softmax<<<BSZ, NT>>>();
    k_out<<<dim3(DD / 128, BSZ / 64, CCLS), NTG>>>(Xb, out);
}

// round 7
// speedup vs baseline: 1.2172x; 1.2172x over previous
#include <cuda_runtime.h>
#include <math.h>
#include <stdint.h>

#define BSZ    2048
#define LATENT 128
#define CCLS   8
#define HID    1024
#define DD     512
#define NMAXX  4096
#define NTG    128
#define NT     256

__constant__ int c_counts[CCLS] = {1024, 1536, 2048, 2560, 3072, 3584, 3840, 4096};

__device__ __align__(16) float g_h[BSZ * HID];
__device__ __align__(16) float g_t[BSZ * HID];
__device__ __align__(16) float g_logits[(size_t)BSZ * NMAXX];
__device__ __align__(16) float g_colmean[CCLS * DD];
__device__ __align__(16) float g_part[2][BSZ * HID];    // gemm_t split-K partials
__device__ __align__(16) float g_opart[4][BSZ * DD];    // k_out split-K partials
__device__ int g_order[BSZ];
__device__ int g_class_off[CCLS + 1];

__device__ __forceinline__ float gelu_exact(float x) {
    return 0.5f * x * (1.0f + erff(x * 0.70710678118654752f));
}
__device__ __forceinline__ uint32_t f2b(float f) { return __float_as_uint(f); }

// exp(x) for |x| <~ 1 via degree-7 Taylor (FMA pipe, no MUFU).
__device__ __forceinline__ float exp_poly(float x) {
    float p = fmaf(x, 1.984126984e-4f, 1.388888889e-3f);
    p = fmaf(x, p, 8.333333333e-3f);
    p = fmaf(x, p, 4.166666667e-2f);
    p = fmaf(x, p, 1.666666667e-1f);
    p = fmaf(x, p, 0.5f);
    p = fmaf(x, p, 1.0f);
    p = fmaf(x, p, 1.0f);
    return p;
}

__device__ __forceinline__ void mma8(float* d, const uint32_t* a, const uint32_t* b) {
    asm volatile(
        "mma.sync.aligned.m16n8k8.row.col.f32.tf32.tf32.f32 "
        "{%0,%1,%2,%3},{%4,%5,%6,%7},{%8,%9},{%0,%1,%2,%3};\n"
        : "+f"(d[0]), "+f"(d[1]), "+f"(d[2]), "+f"(d[3])
        : "r"(a[0]), "r"(a[1]), "r"(a[2]), "r"(a[3]), "r"(b[0]), "r"(b[1]));
}

__device__ __forceinline__ void cpa16(uint32_t dst, const float* src, bool pred) {
    int sz = pred ? 16 : 0;
    asm volatile("cp.async.cg.shared.global [%0], [%1], 16, %2;\n"
                 :: "r"(dst), "l"(src), "r"(sz));
}
#define CP_COMMIT asm volatile("cp.async.commit_group;\n")
#define CP_WAIT2  asm volatile("cp.async.wait_group 2;\n")

#define STAGES 4
#define ASTR 20
#define BSTR 136
#define BS_ELE (16 * BSTR)

// ========================= small config: 64x128, 128 thr ====================
#define AS_ELE_S (64 * ASTR)
#define GEMM_PROLOG_S \
    __shared__ float As[STAGES][AS_ELE_S]; \
    __shared__ float Bs[STAGES][BS_ELE]; \
    int tid = threadIdx.x; int lane = tid & 31; int wid = tid >> 5; \
    int wm = (wid & 1) * 32, wn = (wid >> 1) * 64; \
    int g = lane >> 2, tg = lane & 3; \
    float acc[2][8][4] = {}; \
    uint32_t aBase = (uint32_t)__cvta_generic_to_shared(&As[0][0]); \
    uint32_t bBase = (uint32_t)__cvta_generic_to_shared(&Bs[0][0]); \
    int am = tid >> 1, ak = (tid & 1) * 8; \
    int bkr = tid >> 5, bnr = (tid & 31) * 4;

#define PREF_S(it, buf) do { int _k0 = (it) * 16; \
    cpa16(aBase + (uint32_t)((buf)*AS_ELE_S + am*ASTR + ak)*4,        rA0 + _k0 + ak, pa0); \
    cpa16(aBase + (uint32_t)((buf)*AS_ELE_S + am*ASTR + ak + 4)*4,    rA0 + _k0 + ak + 4, pa0); \
    cpa16(bBase + (uint32_t)((buf)*BS_ELE + bkr*BSTR + bnr)*4,        Bsrc + (size_t)(_k0+bkr)*ldb + bnr, true); \
    cpa16(bBase + (uint32_t)((buf)*BS_ELE + (bkr+4)*BSTR + bnr)*4,    Bsrc + (size_t)(_k0+bkr+4)*ldb + bnr, true); \
    cpa16(bBase + (uint32_t)((buf)*BS_ELE + (bkr+8)*BSTR + bnr)*4,    Bsrc + (size_t)(_k0+bkr+8)*ldb + bnr, true); \
    cpa16(bBase + (uint32_t)((buf)*BS_ELE + (bkr+12)*BSTR + bnr)*4,   Bsrc + (size_t)(_k0+bkr+12)*ldb + bnr, true); \
} while (0)

#define COMPUTE_S(cur) do { \
    const float* AsP = As[cur]; const float* BsP = Bs[cur]; \
    _Pragma("unroll") for (int kk = 0; kk < 2; ++kk) { \
        uint32_t afr[2][4]; \
        _Pragma("unroll") for (int mi = 0; mi < 2; ++mi) { \
            const float* ap = AsP + (wm + mi*16 + g)*ASTR + kk*8 + tg; \
            afr[mi][0] = f2b(ap[0]);  afr[mi][1] = f2b(ap[8*ASTR]); \
            afr[mi][2] = f2b(ap[4]);  afr[mi][3] = f2b(ap[8*ASTR + 4]); } \
        uint32_t bfr[8][2]; \
        _Pragma("unroll") for (int ni = 0; ni < 8; ++ni) { \
            const float* bp = BsP + (kk*8 + tg)*BSTR + wn + ni*8 + g; \
            bfr[ni][0] = f2b(bp[0]);  bfr[ni][1] = f2b(bp[4*BSTR]); } \
        _Pragma("unroll") for (int mi = 0; mi < 2; ++mi) \
        _Pragma("unroll") for (int ni = 0; ni < 8; ++ni) \
            mma8(acc[mi][ni], afr[mi], bfr[ni]); \
    } } while (0)

#define MAINLOOP_S(KITERS) \
    PREF_S(0, 0); CP_COMMIT; \
    PREF_S(1, 1); CP_COMMIT; \
    PREF_S(2, 2); CP_COMMIT; \
    for (int it = 0; it < (KITERS); ++it) { \
        int cur = it & 3; \
        CP_WAIT2; \
        __syncthreads(); \
        int nx = it + STAGES - 1; \
        if (nx < (KITERS)) { PREF_S(nx, nx & 3); } \
        CP_COMMIT; \
        COMPUTE_S(cur); \
    }

// ========================= large config: 128x128, 256 thr ===================
#define AS_ELE_L (128 * ASTR)
#define GEMM_PROLOG_L \
    __shared__ float As[STAGES][AS_ELE_L]; \
    __shared__ float Bs[STAGES][BS_ELE]; \
    int tid = threadIdx.x; int lane = tid & 31; int wid = tid >> 5; \
    int wm = (wid & 3) * 32, wn = (wid >> 2) * 64; \
    int g = lane >> 2, tg = lane & 3; \
    float acc[2][8][4] = {}; \
    uint32_t aBase = (uint32_t)__cvta_generic_to_shared(&As[0][0]); \
    uint32_t bBase = (uint32_t)__cvta_generic_to_shared(&Bs[0][0]); \
    int am = tid >> 1, ak = (tid & 1) * 8; \
    int bkr = tid >> 5, bnr = (tid & 31) * 4;

#define PREF_L(it, buf) do { int _k0 = (it) * 16; \
    cpa16(aBase + (uint32_t)((buf)*AS_ELE_L + am*ASTR + ak)*4,        rA0 + _k0 + ak, pa0); \
    cpa16(aBase + (uint32_t)((buf)*AS_ELE_L + am*ASTR + ak + 4)*4,    rA0 + _k0 + ak + 4, pa0); \
    cpa16(bBase + (uint32_t)((buf)*BS_ELE + bkr*BSTR + bnr)*4,        Bsrc + (size_t)(_k0+bkr)*ldb + bnr, true); \
    cpa16(bBase + (uint32_t)((buf)*BS_ELE + (bkr+8)*BSTR + bnr)*4,    Bsrc + (size_t)(_k0+bkr+8)*ldb + bnr, true); \
} while (0)

#define MAINLOOP_L(KITERS) \
    PREF_L(0, 0); CP_COMMIT; \
    PREF_L(1, 1); CP_COMMIT; \
    PREF_L(2, 2); CP_COMMIT; \
    for (int it = 0; it < (KITERS); ++it) { \
        int cur = it & 3; \
        CP_WAIT2; \
        __syncthreads(); \
        int nx = it + STAGES - 1; \
        if (nx < (KITERS)) { PREF_L(nx, nx & 3); } \
        CP_COMMIT; \
        COMPUTE_S(cur); \
    }

// ---------------------------------------------------------------------------
__global__ void group_kernel(const int* __restrict__ cls) {
    __shared__ int cnt[CCLS];
    __shared__ int off[CCLS + 1];
    int tid = threadIdx.x;
    if (tid < CCLS) cnt[tid] = 0;
    __syncthreads();
    for (int b = tid; b < BSZ; b += blockDim.x) atomicAdd(&cnt[cls[b]], 1);
    __syncthreads();
    if (tid == 0) {
        int s = 0;
        for (int c = 0; c < CCLS; c++) { off[c] = s; s += cnt[c]; }
        off[CCLS] = s;
        for (int c = 0; c <= CCLS; c++) g_class_off[c] = off[c];
    }
    __syncthreads();
    if (tid < CCLS) cnt[tid] = off[tid];
    __syncthreads();
    for (int b = tid; b < BSZ; b += blockDim.x) {
        int c = cls[b];
        int slot = atomicAdd(&cnt[c], 1);
        g_order[slot] = b;
    }
}

// ---------------------------------------------------------------------------
__global__ __launch_bounds__(NT) void k_colmean(const float* __restrict__ Xbuf) {
    int c = blockIdx.y;
    int dl = threadIdx.x & 63;
    int d = blockIdx.x * 64 + dl;
    int stripe = threadIdx.x >> 6;
    int cnt = c_counts[c];
    const float* X = Xbuf + (size_t)c * NMAXX * DD + d;
    float s = 0.f;
#pragma unroll 4
    for (int n = stripe; n < cnt; n += 4) s += X[(size_t)n * DD];
    __shared__ float red[NT];
    red[threadIdx.x] = s;
    __syncthreads();
    if (stripe == 0) {
        float tot = red[dl] + red[dl + 64] + red[dl + 128] + red[dl + 192];
        g_colmean[c * DD + d] = tot / (float)cnt;
    }
}

// ---------------------------------------------------------------------------
// Kernel 1: h = gelu(z @ W1[:128] + W1[128+cid] + b1)   (64x128 tiles)
// ---------------------------------------------------------------------------
__global__ __launch_bounds__(NTG, 4) void k_gemm_h(
    const float* __restrict__ z, const int* __restrict__ cls,
    const float* __restrict__ W1, const float* __restrict__ b1) {
    int m0 = blockIdx.y * 64, n0 = blockIdx.x * 128;
    GEMM_PROLOG_S
    const float* rA0 = z + (size_t)(m0 + am) * LATENT;
    bool pa0 = true;
    const float* Bsrc = W1 + n0; int ldb = HID;
    MAINLOOP_S(8)
#pragma unroll
    for (int mi = 0; mi < 2; ++mi)
#pragma unroll
    for (int r2 = 0; r2 < 2; ++r2) {
        int m = m0 + wm + mi * 16 + g + r2 * 8;
        int cid = cls[m];
        const float* wrow = W1 + (size_t)(LATENT + cid) * HID;
#pragma unroll
        for (int ni = 0; ni < 8; ++ni) {
            int n = n0 + wn + ni * 8 + tg * 2;
            float2 o;
            o.x = gelu_exact(acc[mi][ni][r2 * 2 + 0] + wrow[n] + b1[n]);
            o.y = gelu_exact(acc[mi][ni][r2 * 2 + 1] + wrow[n + 1] + b1[n + 1]);
            *(float2*)(g_h + (size_t)m * HID + n) = o;
        }
    }
}

// ---------------------------------------------------------------------------
// Kernel 2: gemm_t split-K=2: partial[sp] = h[:, sp*512:(sp+1)*512] @ W2-half
// ---------------------------------------------------------------------------
__global__ __launch_bounds__(NTG, 4) void k_gemm_t(const float* __restrict__ W2) {
    int m0 = blockIdx.y * 64, n0 = blockIdx.x * 128;
    int sp = blockIdx.z;
    GEMM_PROLOG_S
    const float* rA0 = g_h + (size_t)(m0 + am) * HID + sp * (HID / 2);
    bool pa0 = true;
    const float* Bsrc = W2 + (size_t)(sp * (HID / 2)) * HID + n0; int ldb = HID;
    MAINLOOP_S(HID / 2 / 16)
    float* dst = g_part[sp];
#pragma unroll
    for (int mi = 0; mi < 2; ++mi)
#pragma unroll
    for (int r2 = 0; r2 < 2; ++r2) {
        int m = m0 + wm + mi * 16 + g + r2 * 8;
#pragma unroll
        for (int ni = 0; ni < 8; ++ni) {
            int n = n0 + wn + ni * 8 + tg * 2;
            float2 o;
            o.x = acc[mi][ni][r2 * 2 + 0];
            o.y = acc[mi][ni][r2 * 2 + 1];
            *(float2*)(dst + (size_t)m * HID + n) = o;
        }
    }
}

// t = gelu(p0 + p1 + b2)
__global__ __launch_bounds__(NT) void k_t_epi(const float* __restrict__ b2) {
    int idx = blockIdx.x * NT + threadIdx.x;        // BSZ*HID/4 quads
    int n = (idx & (HID / 4 - 1)) * 4;
    float4 p0 = *(const float4*)(g_part[0] + (size_t)idx * 4);
    float4 p1 = *(const float4*)(g_part[1] + (size_t)idx * 4);
    float4 bb = *(const float4*)(b2 + n);
    float4 o;
    o.x = gelu_exact(p0.x + p1.x + bb.x);
    o.y = gelu_exact(p0.y + p1.y + bb.y);
    o.z = gelu_exact(p0.z + p1.z + bb.z);
    o.w = gelu_exact(p0.w + p1.w + bb.w);
    *(float4*)(g_t + (size_t)idx * 4) = o;
}

// ---------------------------------------------------------------------------
// Kernel 3: grouped logits, 128x128 tiles @ 256 threads
// ---------------------------------------------------------------------------
__global__ __launch_bounds__(NT, 2) void k_logits(
    const float* __restrict__ Wa, const float* __restrict__ ba) {
    int c = blockIdx.z;
    int off = g_class_off[c];
    int Bc = g_class_off[c + 1] - off;
    int mt = blockIdx.y, nt = blockIdx.x;
    if (mt * 128 >= Bc) return;
    int cnt = c_counts[c];
    if (nt * 128 >= cnt) return;
    int m0 = mt * 128, n0 = nt * 128;
    GEMM_PROLOG_L
    bool pa0 = (m0 + am) < Bc;
    const float* rA0 = pa0 ? g_t + (size_t)g_order[off + m0 + am] * HID : g_t;
    const float* Bsrc = Wa + (size_t)c * HID * NMAXX + n0; int ldb = NMAXX;
    MAINLOOP_L(64)
    const float* baC = ba + (size_t)c * NMAXX;
#pragma unroll
    for (int mi = 0; mi < 2; ++mi)
#pragma unroll
    for (int r2 = 0; r2 < 2; ++r2) {
        int ml = m0 + wm + mi * 16 + g + r2 * 8;
        if (ml < Bc) {
            size_t row = (size_t)(off + ml) * NMAXX;
#pragma unroll
            for (int ni = 0; ni < 8; ++ni) {
                int n = n0 + wn + ni * 8 + tg * 2;
                float2 bb = *(const float2*)(baC + n);
                float2 o;
                o.x = acc[mi][ni][r2 * 2 + 0] + bb.x;
                o.y = acc[mi][ni][r2 * 2 + 1] + bb.y;
                *(float2*)(g_logits + row + n) = o;
            }
        }
    }
}

// ---------------------------------------------------------------------------
// Kernel 4: poly-exp softmax; writes beta = alpha - 1/cnt in place.
// ---------------------------------------------------------------------------
__global__ __launch_bounds__(NT) void k_softmax() {
    __shared__ float buf[NMAXX];
    __shared__ float reds[NT];
    int r = blockIdx.x;
    int c = 0;
#pragma unroll
    for (int i = 1; i < CCLS; i++)
        if (r >= g_class_off[i]) c = i;
    int cnt = c_counts[c];
    float* row = g_logits + (size_t)r * NMAXX;
    int tid = threadIdx.x;

    float s = 0.f;
    for (int i = tid * 4; i < cnt; i += NT * 4) {
        float4 v = *(const float4*)(row + i);
        v.x = exp_poly(v.x); v.y = exp_poly(v.y);
        v.z = exp_poly(v.z); v.w = exp_poly(v.w);
        s += v.x + v.y + v.z + v.w;
        *(float4*)(buf + i) = v;
    }
    reds[tid] = s;
    __syncthreads();
    for (int st = NT / 2; st > 0; st >>= 1) {
        if (tid < st) reds[tid] += reds[tid + st];
        __syncthreads();
    }
    float inv = 1.0f / reds[0];
    float invc = 1.0f / (float)cnt;

    for (int i = tid * 4; i < cnt; i += NT * 4) {
        float4 v = *(const float4*)(buf + i);
        v.x = fmaf(v.x, inv, -invc);
        v.y = fmaf(v.y, inv, -invc);
        v.z = fmaf(v.z, inv, -invc);
        v.w = fmaf(v.w, inv, -invc);
        *(float4*)(row + i) = v;
    }
}

// ---------------------------------------------------------------------------
// Kernel 5: k_out split-K=4: opart[sp][r] = beta[r, koff:koff+cnt/4] @ X-chunk
//   grid (DD/128, 32, CCLS*4)
// ---------------------------------------------------------------------------
__global__ __launch_bounds__(NTG, 4) void k_out(const float* __restrict__ Xbuf) {
    int zc = blockIdx.z;
    int c = zc >> 2, sp = zc & 3;
    int off = g_class_off[c];
    int Bc = g_class_off[c + 1] - off;
    int mt = blockIdx.y, nt = blockIdx.x;
    if (mt * 64 >= Bc) return;
    int cnt = c_counts[c];
    int koff = sp * (cnt >> 2);
    int m0 = mt * 64, n0 = nt * 128;
    GEMM_PROLOG_S
    bool pa0 = (m0 + am) < Bc;
    const float* rA0 = pa0 ? g_logits + (size_t)(off + m0 + am) * NMAXX + koff : g_logits;
    const float* Bsrc = Xbuf + (size_t)c * NMAXX * DD + (size_t)koff * DD + n0; int ldb = DD;
    int kit = cnt >> 6;   // (cnt/4)/16
    MAINLOOP_S(kit)
    float* dst = g_opart[sp];
#pragma unroll
    for (int mi = 0; mi < 2; ++mi)
#pragma unroll
    for (int r2 = 0; r2 < 2; ++r2) {
        int ml = m0 + wm + mi * 16 + g + r2 * 8;
        if (ml < Bc) {
            size_t row = (size_t)(off + ml) * DD;
#pragma unroll
            for (int ni = 0; ni < 8; ++ni) {
                int n = n0 + wn + ni * 8 + tg * 2;
                float2 o;
                o.x = acc[mi][ni][r2 * 2 + 0];
                o.y = acc[mi][ni][r2 * 2 + 1];
                *(float2*)(dst + row + n) = o;
            }
        }
    }
}

// out[order[r]] = colmean[c] + sum_sp opart[sp][r]
__global__ __launch_bounds__(NT) void k_out_epi(float* __restrict__ out) {
    int idx = blockIdx.x * NT + threadIdx.x;        // BSZ*DD/4 quads
    int r = idx >> (7);                              // DD/4 = 128 quads per row
    int n = (idx & 127) * 4;
    int c = 0;
#pragma unroll
    for (int i = 1; i < CCLS; i++)
        if (r >= g_class_off[i]) c = i;
    int b = g_order[r];
    size_t o4 = (size_t)r * DD + n;
    float4 p0 = *(const float4*)(g_opart[0] + o4);
    float4 p1 = *(const float4*)(g_opart[1] + o4);
    float4 p2 = *(const float4*)(g_opart[2] + o4);
    float4 p3 = *(const float4*)(g_opart[3] + o4);
    float4 cm = *(const float4*)(g_colmean + c * DD + n);
    float4 o;
    o.x = cm.x + ((p0.x + p1.x) + (p2.x + p3.x));
    o.y = cm.y + ((p0.y + p1.y) + (p2.y + p3.y));
    o.z = cm.z + ((p0.z + p1.z) + (p2.z + p3.z));
    o.w = cm.w + ((p0.w + p1.w) + (p2.w + p3.w));
    *(float4*)(out + (size_t)b * DD + n) = o;
}

// ---------------------------------------------------------------------------
extern "C" void kernel_launch(void* const* d_in, const int* in_sizes, int n_in,
                              void* d_out, int out_size) {
    const float* z   = (const float*)d_in[0];
    const int*   cls = (const int*)d_in[1];
    const float* W1  = (const float*)d_in[2];
    const float* b1  = (const float*)d_in[3];
    const float* W2  = (const float*)d_in[4];
    const float* b2  = (const float*)d_in[5];
    const float* Wa  = (const float*)d_in[6];
    const float* ba  = (const float*)d_in[7];
    const float* Xb  = (const float*)d_in[8];
    float* out = (float*)d_out;

    group_kernel<<<1, NT>>>(cls);
    k_colmean<<<dim3(DD / 64, CCLS), NT>>>(Xb);
    k_gemm_h<<<dim3(HID / 128, BSZ / 64), NTG>>>(z, cls, W1, b1);
    k_gemm_t<<<dim3(HID / 128, BSZ / 64, 2), NTG>>>(W2);
    k_t_epi<<<BSZ * HID / 4 / NT, NT>>>(b2);
    k_logits<<<dim3(NMAXX / 128, BSZ / 128, CCLS), NT>>>(Wa, ba);
    k_softmax<<<BSZ, NT>>>();
    k_out<<<dim3(DD / 128, BSZ / 64, CCLS * 4), NTG>>>(Xb);
    k_out_epi<<<BSZ * DD / 4 / NT, NT>>>(out);
}

// round 11
// speedup vs baseline: 1.2541x; 1.0303x over previous
#include <cuda_runtime.h>
#include <math.h>
#include <stdint.h>

#define BSZ    2048
#define LATENT 128
#define CCLS   8
#define HID    1024
#define DD     512
#define NMAXX  4096
#define NTG    128
#define NT     256

__constant__ int c_counts[CCLS] = {1024, 1536, 2048, 2560, 3072, 3584, 3840, 4096};

__device__ __align__(16) float g_h[BSZ * HID];
__device__ __align__(16) float g_t[BSZ * HID];
__device__ __align__(16) float g_logits[(size_t)BSZ * NMAXX];
__device__ __align__(16) float g_lpart[2][(size_t)BSZ * NMAXX];  // logits split-K partials
__device__ __align__(16) float g_colmean[CCLS * DD];
__device__ __align__(16) float g_part[4][BSZ * HID];             // gemm_t split-K partials
__device__ __align__(16) float g_opart[4][BSZ * DD];             // k_out split-K partials
__device__ int g_order[BSZ];
__device__ int g_class_off[CCLS + 1];

__device__ __forceinline__ float gelu_exact(float x) {
    return 0.5f * x * (1.0f + erff(x * 0.70710678118654752f));
}
__device__ __forceinline__ uint32_t f2b(float f) { return __float_as_uint(f); }

// exp(x) for |x| <~ 1 via degree-7 Taylor (FMA pipe, no MUFU).
__device__ __forceinline__ float exp_poly(float x) {
    float p = fmaf(x, 1.984126984e-4f, 1.388888889e-3f);
    p = fmaf(x, p, 8.333333333e-3f);
    p = fmaf(x, p, 4.166666667e-2f);
    p = fmaf(x, p, 1.666666667e-1f);
    p = fmaf(x, p, 0.5f);
    p = fmaf(x, p, 1.0f);
    p = fmaf(x, p, 1.0f);
    return p;
}

__device__ __forceinline__ void mma8(float* d, const uint32_t* a, const uint32_t* b) {
    asm volatile(
        "mma.sync.aligned.m16n8k8.row.col.f32.tf32.tf32.f32 "
        "{%0,%1,%2,%3},{%4,%5,%6,%7},{%8,%9},{%0,%1,%2,%3};\n"
        : "+f"(d[0]), "+f"(d[1]), "+f"(d[2]), "+f"(d[3])
        : "r"(a[0]), "r"(a[1]), "r"(a[2]), "r"(a[3]), "r"(b[0]), "r"(b[1]));
}

__device__ __forceinline__ void cpa16(uint32_t dst, const float* src, bool pred) {
    int sz = pred ? 16 : 0;  // sz=0 -> zero-fill (deterministic)
    asm volatile("cp.async.cg.shared.global [%0], [%1], 16, %2;\n"
                 :: "r"(dst), "l"(src), "r"(sz));
}
#define CP_COMMIT asm volatile("cp.async.commit_group;\n")
#define CP_WAIT2  asm volatile("cp.async.wait_group 2;\n")

#define STAGES 4
#define ASTR 20
#define BSTR 136
#define BS_ELE (16 * BSTR)

// ========================= small config: 64x128, 128 thr ====================
#define AS_ELE_S (64 * ASTR)
#define GEMM_PROLOG_S \
    __shared__ float As[STAGES][AS_ELE_S]; \
    __shared__ float Bs[STAGES][BS_ELE]; \
    int tid = threadIdx.x; int lane = tid & 31; int wid = tid >> 5; \
    int wm = (wid & 1) * 32, wn = (wid >> 1) * 64; \
    int g = lane >> 2, tg = lane & 3; \
    float acc[2][8][4] = {}; \
    uint32_t aBase = (uint32_t)__cvta_generic_to_shared(&As[0][0]); \
    uint32_t bBase = (uint32_t)__cvta_generic_to_shared(&Bs[0][0]); \
    int am = tid >> 1, ak = (tid & 1) * 8; \
    int bkr = tid >> 5, bnr = (tid & 31) * 4;

#define PREF_S(it, buf) do { int _k0 = (it) * 16; \
    cpa16(aBase + (uint32_t)((buf)*AS_ELE_S + am*ASTR + ak)*4,        rA0 + _k0 + ak, pa0); \
    cpa16(aBase + (uint32_t)((buf)*AS_ELE_S + am*ASTR + ak + 4)*4,    rA0 + _k0 + ak + 4, pa0); \
    cpa16(bBase + (uint32_t)((buf)*BS_ELE + bkr*BSTR + bnr)*4,        Bsrc + (size_t)(_k0+bkr)*ldb + bnr, true); \
    cpa16(bBase + (uint32_t)((buf)*BS_ELE + (bkr+4)*BSTR + bnr)*4,    Bsrc + (size_t)(_k0+bkr+4)*ldb + bnr, true); \
    cpa16(bBase + (uint32_t)((buf)*BS_ELE + (bkr+8)*BSTR + bnr)*4,    Bsrc + (size_t)(_k0+bkr+8)*ldb + bnr, true); \
    cpa16(bBase + (uint32_t)((buf)*BS_ELE + (bkr+12)*BSTR + bnr)*4,   Bsrc + (size_t)(_k0+bkr+12)*ldb + bnr, true); \
} while (0)

#define COMPUTE_S(cur) do { \
    const float* AsP = As[cur]; const float* BsP = Bs[cur]; \
    _Pragma("unroll") for (int kk = 0; kk < 2; ++kk) { \
        uint32_t afr[2][4]; \
        _Pragma("unroll") for (int mi = 0; mi < 2; ++mi) { \
            const float* ap = AsP + (wm + mi*16 + g)*ASTR + kk*8 + tg; \
            afr[mi][0] = f2b(ap[0]);  afr[mi][1] = f2b(ap[8*ASTR]); \
            afr[mi][2] = f2b(ap[4]);  afr[mi][3] = f2b(ap[8*ASTR + 4]); } \
        uint32_t bfr[8][2]; \
        _Pragma("unroll") for (int ni = 0; ni < 8; ++ni) { \
            const float* bp = BsP + (kk*8 + tg)*BSTR + wn + ni*8 + g; \
            bfr[ni][0] = f2b(bp[0]);  bfr[ni][1] = f2b(bp[4*BSTR]); } \
        _Pragma("unroll") for (int mi = 0; mi < 2; ++mi) \
        _Pragma("unroll") for (int ni = 0; ni < 8; ++ni) \
            mma8(acc[mi][ni], afr[mi], bfr[ni]); \
    } } while (0)

#define MAINLOOP_S(KITERS) \
    PREF_S(0, 0); CP_COMMIT; \
    PREF_S(1, 1); CP_COMMIT; \
    PREF_S(2, 2); CP_COMMIT; \
    for (int it = 0; it < (KITERS); ++it) { \
        int cur = it & 3; \
        CP_WAIT2; \
        __syncthreads(); \
        int nx = it + STAGES - 1; \
        if (nx < (KITERS)) { PREF_S(nx, nx & 3); } \
        CP_COMMIT; \
        COMPUTE_S(cur); \
    }

// ========================= large config: 128x128, 256 thr ===================
#define AS_ELE_L (128 * ASTR)
#define GEMM_PROLOG_L \
    __shared__ float As[STAGES][AS_ELE_L]; \
    __shared__ float Bs[STAGES][BS_ELE]; \
    int tid = threadIdx.x; int lane = tid & 31; int wid = tid >> 5; \
    int wm = (wid & 3) * 32, wn = (wid >> 2) * 64; \
    int g = lane >> 2, tg = lane & 3; \
    float acc[2][8][4] = {}; \
    uint32_t aBase = (uint32_t)__cvta_generic_to_shared(&As[0][0]); \
    uint32_t bBase = (uint32_t)__cvta_generic_to_shared(&Bs[0][0]); \
    int am = tid >> 1, ak = (tid & 1) * 8; \
    int bkr = tid >> 5, bnr = (tid & 31) * 4;

#define PREF_L(it, buf) do { int _k0 = (it) * 16; \
    cpa16(aBase + (uint32_t)((buf)*AS_ELE_L + am*ASTR + ak)*4,        rA0 + _k0 + ak, pa0); \
    cpa16(aBase + (uint32_t)((buf)*AS_ELE_L + am*ASTR + ak + 4)*4,    rA0 + _k0 + ak + 4, pa0); \
    cpa16(bBase + (uint32_t)((buf)*BS_ELE + bkr*BSTR + bnr)*4,        Bsrc + (size_t)(_k0+bkr)*ldb + bnr, true); \
    cpa16(bBase + (uint32_t)((buf)*BS_ELE + (bkr+8)*BSTR + bnr)*4,    Bsrc + (size_t)(_k0+bkr+8)*ldb + bnr, true); \
} while (0)

#define MAINLOOP_L(KITERS) \
    PREF_L(0, 0); CP_COMMIT; \
    PREF_L(1, 1); CP_COMMIT; \
    PREF_L(2, 2); CP_COMMIT; \
    for (int it = 0; it < (KITERS); ++it) { \
        int cur = it & 3; \
        CP_WAIT2; \
        __syncthreads(); \
        int nx = it + STAGES - 1; \
        if (nx < (KITERS)) { PREF_L(nx, nx & 3); } \
        CP_COMMIT; \
        COMPUTE_S(cur); \
    }

// ---------------------------------------------------------------------------
__global__ void group_kernel(const int* __restrict__ cls) {
    __shared__ int cnt[CCLS];
    __shared__ int off[CCLS + 1];
    int tid = threadIdx.x;
    if (tid < CCLS) cnt[tid] = 0;
    __syncthreads();
    for (int b = tid; b < BSZ; b += blockDim.x) atomicAdd(&cnt[cls[b]], 1);
    __syncthreads();
    if (tid == 0) {
        int s = 0;
        for (int c = 0; c < CCLS; c++) { off[c] = s; s += cnt[c]; }
        off[CCLS] = s;
        for (int c = 0; c <= CCLS; c++) g_class_off[c] = off[c];
    }
    __syncthreads();
    if (tid < CCLS) cnt[tid] = off[tid];
    __syncthreads();
    for (int b = tid; b < BSZ; b += blockDim.x) {
        int c = cls[b];
        int slot = atomicAdd(&cnt[c], 1);
        g_order[slot] = b;
    }
}

// ---------------------------------------------------------------------------
__global__ __launch_bounds__(NT) void k_colmean(const float* __restrict__ Xbuf) {
    int c = blockIdx.y;
    int dl = threadIdx.x & 63;
    int d = blockIdx.x * 64 + dl;
    int stripe = threadIdx.x >> 6;
    int cnt = c_counts[c];
    const float* X = Xbuf + (size_t)c * NMAXX * DD + d;
    float s = 0.f;
#pragma unroll 4
    for (int n = stripe; n < cnt; n += 4) s += X[(size_t)n * DD];
    __shared__ float red[NT];
    red[threadIdx.x] = s;
    __syncthreads();
    if (stripe == 0) {
        float tot = red[dl] + red[dl + 64] + red[dl + 128] + red[dl + 192];
        g_colmean[c * DD + d] = tot / (float)cnt;
    }
}

// ---------------------------------------------------------------------------
// Kernel 1: h = gelu(z @ W1[:128] + W1[128+cid] + b1)
// ---------------------------------------------------------------------------
__global__ __launch_bounds__(NTG, 4) void k_gemm_h(
    const float* __restrict__ z, const int* __restrict__ cls,
    const float* __restrict__ W1, const float* __restrict__ b1) {
    int m0 = blockIdx.y * 64, n0 = blockIdx.x * 128;
    GEMM_PROLOG_S
    const float* rA0 = z + (size_t)(m0 + am) * LATENT;
    bool pa0 = true;
    const float* Bsrc = W1 + n0; int ldb = HID;
    MAINLOOP_S(8)
#pragma unroll
    for (int mi = 0; mi < 2; ++mi)
#pragma unroll
    for (int r2 = 0; r2 < 2; ++r2) {
        int m = m0 + wm + mi * 16 + g + r2 * 8;
        int cid = cls[m];
        const float* wrow = W1 + (size_t)(LATENT + cid) * HID;
#pragma unroll
        for (int ni = 0; ni < 8; ++ni) {
            int n = n0 + wn + ni * 8 + tg * 2;
            float2 o;
            o.x = gelu_exact(acc[mi][ni][r2 * 2 + 0] + wrow[n] + b1[n]);
            o.y = gelu_exact(acc[mi][ni][r2 * 2 + 1] + wrow[n + 1] + b1[n + 1]);
            *(float2*)(g_h + (size_t)m * HID + n) = o;
        }
    }
}

// ---------------------------------------------------------------------------
// Kernel 2: gemm_t split-K=4: partial[sp] = h[:, sp*256:+256] @ W2-chunk
// ---------------------------------------------------------------------------
__global__ __launch_bounds__(NTG, 4) void k_gemm_t(const float* __restrict__ W2) {
    int m0 = blockIdx.y * 64, n0 = blockIdx.x * 128;
    int sp = blockIdx.z;
    GEMM_PROLOG_S
    const float* rA0 = g_h + (size_t)(m0 + am) * HID + sp * (HID / 4);
    bool pa0 = true;
    const float* Bsrc = W2 + (size_t)(sp * (HID / 4)) * HID + n0; int ldb = HID;
    MAINLOOP_S(HID / 4 / 16)
    float* dst = g_part[sp];
#pragma unroll
    for (int mi = 0; mi < 2; ++mi)
#pragma unroll
    for (int r2 = 0; r2 < 2; ++r2) {
        int m = m0 + wm + mi * 16 + g + r2 * 8;
#pragma unroll
        for (int ni = 0; ni < 8; ++ni) {
            int n = n0 + wn + ni * 8 + tg * 2;
            float2 o;
            o.x = acc[mi][ni][r2 * 2 + 0];
            o.y = acc[mi][ni][r2 * 2 + 1];
            *(float2*)(dst + (size_t)m * HID + n) = o;
        }
    }
}

// t = gelu(p0+p1+p2+p3+b2)
__global__ __launch_bounds__(NT) void k_t_epi(const float* __restrict__ b2) {
    int idx = blockIdx.x * NT + threadIdx.x;
    int n = (idx & (HID / 4 - 1)) * 4;
    float4 p0 = *(const float4*)(g_part[0] + (size_t)idx * 4);
    float4 p1 = *(const float4*)(g_part[1] + (size_t)idx * 4);
    float4 p2 = *(const float4*)(g_part[2] + (size_t)idx * 4);
    float4 p3 = *(const float4*)(g_part[3] + (size_t)idx * 4);
    float4 bb = *(const float4*)(b2 + n);
    float4 o;
    o.x = gelu_exact(((p0.x + p1.x) + (p2.x + p3.x)) + bb.x);
    o.y = gelu_exact(((p0.y + p1.y) + (p2.y + p3.y)) + bb.y);
    o.z = gelu_exact(((p0.z + p1.z) + (p2.z + p3.z)) + bb.z);
    o.w = gelu_exact(((p0.w + p1.w) + (p2.w + p3.w)) + bb.w);
    *(float4*)(g_t + (size_t)idx * 4) = o;
}

// ---------------------------------------------------------------------------
// Kernel 3: grouped logits split-K=2, 128x128 tiles @ 256 threads.
//   lpart[sp][r, n] = t[order[r], sp*512:+512] . Wa[c][sp*512:+512, n]
//   grid (NMAXX/128, BSZ/128, CCLS*2)
// ---------------------------------------------------------------------------
__global__ __launch_bounds__(NT, 2) void k_logits(const float* __restrict__ Wa) {
    int zc = blockIdx.z;
    int c = zc >> 1, sp = zc & 1;
    int off = g_class_off[c];
    int Bc = g_class_off[c + 1] - off;
    int mt = blockIdx.y, nt = blockIdx.x;
    if (mt * 128 >= Bc) return;
    int cnt = c_counts[c];
    if (nt * 128 >= cnt) return;
    int m0 = mt * 128, n0 = nt * 128;
    GEMM_PROLOG_L
    bool pa0 = (m0 + am) < Bc;
    const float* rA0 = (pa0 ? g_t + (size_t)g_order[off + m0 + am] * HID : g_t)
                       + sp * (HID / 2);
    const float* Bsrc = Wa + (size_t)c * HID * NMAXX
                        + (size_t)(sp * (HID / 2)) * NMAXX + n0;
    int ldb = NMAXX;
    MAINLOOP_L(HID / 2 / 16)
    float* dst = g_lpart[sp];
#pragma unroll
    for (int mi = 0; mi < 2; ++mi)
#pragma unroll
    for (int r2 = 0; r2 < 2; ++r2) {
        int ml = m0 + wm + mi * 16 + g + r2 * 8;
        if (ml < Bc) {
            size_t row = (size_t)(off + ml) * NMAXX;
#pragma unroll
            for (int ni = 0; ni < 8; ++ni) {
                int n = n0 + wn + ni * 8 + tg * 2;
                float2 o;
                o.x = acc[mi][ni][r2 * 2 + 0];
                o.y = acc[mi][ni][r2 * 2 + 1];
                *(float2*)(dst + row + n) = o;
            }
        }
    }
}

// ---------------------------------------------------------------------------
// Kernel 4: softmax fused with split-K merge + bias:
//   l = p0 + p1 + ba;  beta = exp_poly(l)/sum - 1/cnt  -> g_logits
// ---------------------------------------------------------------------------
__global__ __launch_bounds__(NT) void k_softmax(const float* __restrict__ ba) {
    __shared__ float buf[NMAXX];
    __shared__ float reds[NT];
    int r = blockIdx.x;
    int c = 0;
#pragma unroll
    for (int i = 1; i < CCLS; i++)
        if (r >= g_class_off[i]) c = i;
    int cnt = c_counts[c];
    const float* p0 = g_lpart[0] + (size_t)r * NMAXX;
    const float* p1 = g_lpart[1] + (size_t)r * NMAXX;
    const float* baC = ba + (size_t)c * NMAXX;
    float* row = g_logits + (size_t)r * NMAXX;
    int tid = threadIdx.x;

    float s = 0.f;
    for (int i = tid * 4; i < cnt; i += NT * 4) {
        float4 a = *(const float4*)(p0 + i);
        float4 b = *(const float4*)(p1 + i);
        float4 bb = *(const float4*)(baC + i);
        float4 v;
        v.x = exp_poly(a.x + b.x + bb.x);
        v.y = exp_poly(a.y + b.y + bb.y);
        v.z = exp_poly(a.z + b.z + bb.z);
        v.w = exp_poly(a.w + b.w + bb.w);
        s += v.x + v.y + v.z + v.w;
        *(float4*)(buf + i) = v;
    }
    reds[tid] = s;
    __syncthreads();
    for (int st = NT / 2; st > 0; st >>= 1) {
        if (tid < st) reds[tid] += reds[tid + st];
        __syncthreads();
    }
    float inv = 1.0f / reds[0];
    float invc = 1.0f / (float)cnt;

    for (int i = tid * 4; i < cnt; i += NT * 4) {
        float4 v = *(const float4*)(buf + i);
        v.x = fmaf(v.x, inv, -invc);
        v.y = fmaf(v.y, inv, -invc);
        v.z = fmaf(v.z, inv, -invc);
        v.w = fmaf(v.w, inv, -invc);
        *(float4*)(row + i) = v;
    }
}

// ---------------------------------------------------------------------------
// Kernel 5: k_out split-K=4: opart[sp][r] = beta[r, koff:+cnt/4] @ X-chunk
// ---------------------------------------------------------------------------
__global__ __launch_bounds__(NTG, 4) void k_out(const float* __restrict__ Xbuf) {
    int zc = blockIdx.z;
    int c = zc >> 2, sp = zc & 3;
    int off = g_class_off[c];
    int Bc = g_class_off[c + 1] - off;
    int mt = blockIdx.y, nt = blockIdx.x;
    if (mt * 64 >= Bc) return;
    int cnt = c_counts[c];
    int koff = sp * (cnt >> 2);
    int m0 = mt * 64, n0 = nt * 128;
    GEMM_PROLOG_S
    bool pa0 = (m0 + am) < Bc;
    const float* rA0 = pa0 ? g_logits + (size_t)(off + m0 + am) * NMAXX + koff : g_logits;
    const float* Bsrc = Xbuf + (size_t)c * NMAXX * DD + (size_t)koff * DD + n0; int ldb = DD;
    int kit = cnt >> 6;
    MAINLOOP_S(kit)
    float* dst = g_opart[sp];
#pragma unroll
    for (int mi = 0; mi < 2; ++mi)
#pragma unroll
    for (int r2 = 0; r2 < 2; ++r2) {
        int ml = m0 + wm + mi * 16 + g + r2 * 8;
        if (ml < Bc) {
            size_t row = (size_t)(off + ml) * DD;
#pragma unroll
            for (int ni = 0; ni < 8; ++ni) {
                int n = n0 + wn + ni * 8 + tg * 2;
                float2 o;
                o.x = acc[mi][ni][r2 * 2 + 0];
                o.y = acc[mi][ni][r2 * 2 + 1];
                *(float2*)(dst + row + n) = o;
            }
        }
    }
}

__global__ __launch_bounds__(NT) void k_out_epi(float* __restrict__ out) {
    int idx = blockIdx.x * NT + threadIdx.x;
    int r = idx >> 7;
    int n = (idx & 127) * 4;
    int c = 0;
#pragma unroll
    for (int i = 1; i < CCLS; i++)
        if (r >= g_class_off[i]) c = i;
    int b = g_order[r];
    size_t o4 = (size_t)r * DD + n;
    float4 p0 = *(const float4*)(g_opart[0] + o4);
    float4 p1 = *(const float4*)(g_opart[1] + o4);
    float4 p2 = *(const float4*)(g_opart[2] + o4);
    float4 p3 = *(const float4*)(g_opart[3] + o4);
    float4 cm = *(const float4*)(g_colmean + c * DD + n);
    float4 o;
    o.x = cm.x + ((p0.x + p1.x) + (p2.x + p3.x));
    o.y = cm.y + ((p0.y + p1.y) + (p2.y + p3.y));
    o.z = cm.z + ((p0.z + p1.z) + (p2.z + p3.z));
    o.w = cm.w + ((p0.w + p1.w) + (p2.w + p3.w));
    *(float4*)(out + (size_t)b * DD + n) = o;
}

// ---------------------------------------------------------------------------
extern "C" void kernel_launch(void* const* d_in, const int* in_sizes, int n_in,
                              void* d_out, int out_size) {
    const float* z   = (const float*)d_in[0];
    const int*   cls = (const int*)d_in[1];
    const float* W1  = (const float*)d_in[2];
    const float* b1  = (const float*)d_in[3];
    const float* W2  = (const float*)d_in[4];
    const float* b2  = (const float*)d_in[5];
    const float* Wa  = (const float*)d_in[6];
    const float* ba  = (const float*)d_in[7];
    const float* Xb  = (const float*)d_in[8];
    float* out = (float*)d_out;

    group_kernel<<<1, NT>>>(cls);
    k_colmean<<<dim3(DD / 64, CCLS), NT>>>(Xb);
    k_gemm_h<<<dim3(HID / 128, BSZ / 64), NTG>>>(z, cls, W1, b1);
    k_gemm_t<<<dim3(HID / 128, BSZ / 64, 4), NTG>>>(W2);
    k_t_epi<<<BSZ * HID / 4 / NT, NT>>>(b2);
    k_logits<<<dim3(NMAXX / 128, BSZ / 128, CCLS * 2), NT>>>(Wa);
    k_softmax<<<BSZ, NT>>>(ba);
    k_out<<<dim3(DD / 128, BSZ / 64, CCLS * 4), NTG>>>(Xb);
    k_out_epi<<<BSZ * DD / 4 / NT, NT>>>(out);
}